// round 16
// baseline (speedup 1.0000x reference)
#include <cuda_runtime.h>
#include <cstdint>

// ---------------------------------------------------------------------------
// 2-layer GAT (heads=2), CSR-based. FFMA2 GEMM with fused attention epilogue,
// packed-f32x2 node softmax-aggregate. CSR builds on side streams; layer-2
// GEMM row-split and pipelined against layer-1 node aggregation.
// ---------------------------------------------------------------------------

#define NN 50000
#define NE 800000

typedef unsigned long long ull;

__device__ float g_xl1[NN * 128];
__device__ float g_out1[NN * 128];
__device__ float g_xl2[NN * 256];
__device__ float g_asrc1[NN * 2];
__device__ float g_adst1[NN * 2];
__device__ float g_asrc2[NN * 2];
__device__ float g_adst2[NN * 2];

// per-layer CSR buffers (cnt must be zero at entry; scanC re-zeroes)
__device__ int g_cnt1[NN],  g_cnt2[NN];
__device__ int g_rowptr1[NN + 1], g_rowptr2[NN + 1];
__device__ int g_off1[NN],  g_off2[NN];
__device__ int g_col1[NE],  g_col2[NE];
__device__ int g_bsum1[32], g_bsum2[32];

__device__ __forceinline__ float leaky(float a) { return a > 0.f ? a : 0.2f * a; }

__device__ __forceinline__ void fma_f32x2(ull& c, ull a, ull b) {
    asm("fma.rn.f32x2 %0, %1, %2, %0;" : "+l"(c) : "l"(a), "l"(b));
}
__device__ __forceinline__ float2 unpack2(ull v) {
    float lo, hi;
    asm("mov.b64 {%0,%1}, %2;" : "=f"(lo), "=f"(hi) : "l"(v));
    return make_float2(lo, hi);
}
__device__ __forceinline__ ull pack2(float f) {
    ull r;
    asm("mov.b64 %0, {%1,%1};" : "=l"(r) : "f"(f));
    return r;
}

// ---------------------------------------------------------------------------
// Packed GEMM + fused attention epilogue. Covers rows [base, Mend) with
// grid.x * 64 rows starting at base.
// ---------------------------------------------------------------------------
template <int KTOT, int NC>
__global__ __launch_bounds__(256)
void gemm_kernel(const float* __restrict__ A, const float* __restrict__ B,
                 const float* __restrict__ att_s, const float* __restrict__ att_d,
                 float* __restrict__ asrc, float* __restrict__ adst,
                 float* __restrict__ C, int base, int Mend)
{
    constexpr int TM = 64, BK = 32;
    constexpr int RM = 8;
    constexpr int RN2 = NC / 64;
    const unsigned FULL = 0xffffffffu;

    __shared__ float2 sA2[BK][TM + 1];
    __shared__ float  sB[BK][NC];

    const int tid = threadIdx.x;
    const int tx = tid & 31, ty = tid >> 5;
    const int m0 = base + blockIdx.x * TM;

    ull acc2[RM][RN2];
#pragma unroll
    for (int i = 0; i < RM; i++)
#pragma unroll
        for (int j = 0; j < RN2; j++) acc2[i][j] = 0ull;

    for (int k0 = 0; k0 < KTOT; k0 += BK) {
#pragma unroll
        for (int i = 0; i < (TM * BK) / 256; i++) {
            int idx = tid + 256 * i;
            int r = idx >> 5;
            int kk = idx & 31;
            int row = m0 + r;
            float v = (row < Mend) ? A[(size_t)row * KTOT + k0 + kk] : 0.f;
            sA2[kk][r] = make_float2(v, v);
        }
#pragma unroll
        for (int i = 0; i < (BK * NC) / 256; i++) {
            int idx = tid + 256 * i;
            int kk = idx / NC;
            int c  = idx % NC;
            sB[kk][c] = B[(size_t)(k0 + kk) * NC + c];
        }
        __syncthreads();

#pragma unroll 4
        for (int kk = 0; kk < BK; kk++) {
            ull xv[RM], wv[RN2];
#pragma unroll
            for (int i = 0; i < RM; i++)
                xv[i] = *(const ull*)&sA2[kk][ty * RM + i];
#pragma unroll
            for (int j = 0; j < RN2; j++)
                wv[j] = *(const ull*)&sB[kk][64 * j + 2 * tx];
#pragma unroll
            for (int i = 0; i < RM; i++)
#pragma unroll
                for (int j = 0; j < RN2; j++)
                    fma_f32x2(acc2[i][j], xv[i], wv[j]);
        }
        __syncthreads();
    }

    float2 asv[RN2], adv[RN2];
#pragma unroll
    for (int j = 0; j < RN2; j++) {
        asv[j] = *(const float2*)&att_s[64 * j + 2 * tx];
        adv[j] = *(const float2*)&att_d[64 * j + 2 * tx];
    }
#pragma unroll
    for (int i = 0; i < RM; i++) {
        int row = m0 + ty * RM + i;
        if (row >= Mend) continue;
        float s0 = 0.f, s1 = 0.f, d0 = 0.f, d1 = 0.f;
#pragma unroll
        for (int j = 0; j < RN2; j++) {
            float2 c = unpack2(acc2[i][j]);
            *(float2*)&C[(size_t)row * NC + 64 * j + 2 * tx] = c;
            float ps = c.x * asv[j].x + c.y * asv[j].y;
            float pd = c.x * adv[j].x + c.y * adv[j].y;
            if (j < RN2 / 2) { s0 += ps; d0 += pd; }
            else             { s1 += ps; d1 += pd; }
        }
#pragma unroll
        for (int o = 16; o > 0; o >>= 1) {
            s0 += __shfl_xor_sync(FULL, s0, o);
            s1 += __shfl_xor_sync(FULL, s1, o);
            d0 += __shfl_xor_sync(FULL, d0, o);
            d1 += __shfl_xor_sync(FULL, d1, o);
        }
        if (tx == 0) {
            asrc[2 * row] = s0; asrc[2 * row + 1] = s1;
            adst[2 * row] = d0; adst[2 * row + 1] = d1;
        }
    }
}

// ---------------------------------------------------------------------------
// CSR construction (vectorized hist/scatter: 2 edges per thread).
// ---------------------------------------------------------------------------
__global__ void hist_kernel(const int* __restrict__ dst, int* __restrict__ cnt, int ne)
{
    int i = blockIdx.x * blockDim.x + threadIdx.x;
    int j = 2 * i;
    if (j + 1 < ne) {
        int2 d = *(const int2*)&dst[j];
        atomicAdd(&cnt[d.x], 1);
        atomicAdd(&cnt[d.y], 1);
    } else if (j < ne) {
        atomicAdd(&cnt[dst[j]], 1);
    }
}

__global__ __launch_bounds__(1024)
void scanA_kernel(const int* __restrict__ cnt, int* __restrict__ rowptr,
                  int* __restrict__ bsum, int n)
{
    __shared__ int wsum[32];
    int tid = threadIdx.x, lane = tid & 31, wid = tid >> 5;
    int i0 = blockIdx.x * 4096 + tid * 4;

    int c0 = 0, c1 = 0, c2 = 0, c3 = 0;
    if (i0 + 3 < n) {
        int4 t = *(const int4*)&cnt[i0];
        c0 = t.x; c1 = t.y; c2 = t.z; c3 = t.w;
    } else {
        if (i0     < n) c0 = cnt[i0];
        if (i0 + 1 < n) c1 = cnt[i0 + 1];
        if (i0 + 2 < n) c2 = cnt[i0 + 2];
        if (i0 + 3 < n) c3 = cnt[i0 + 3];
    }
    int v = c0 + c1 + c2 + c3;
    int s = v;
#pragma unroll
    for (int o = 1; o < 32; o <<= 1) {
        int t = __shfl_up_sync(0xffffffffu, s, o);
        if (lane >= o) s += t;
    }
    if (lane == 31) wsum[wid] = s;
    __syncthreads();
    if (wid == 0) {
        int ws = wsum[lane];
#pragma unroll
        for (int o = 1; o < 32; o <<= 1) {
            int t = __shfl_up_sync(0xffffffffu, ws, o);
            if (lane >= o) ws += t;
        }
        wsum[lane] = ws;
    }
    __syncthreads();
    int excl = s - v + (wid ? wsum[wid - 1] : 0);
    int e0 = excl, e1 = e0 + c0, e2 = e1 + c1, e3 = e2 + c2;
    if (i0     < n) rowptr[i0]     = e0;
    if (i0 + 1 < n) rowptr[i0 + 1] = e1;
    if (i0 + 2 < n) rowptr[i0 + 2] = e2;
    if (i0 + 3 < n) rowptr[i0 + 3] = e3;
    if (tid == 0) bsum[blockIdx.x] = wsum[31];
}

// scanC with fused scanB: warp 0 of every block redundantly scans bsum.
__global__ __launch_bounds__(256)
void scanC_kernel(int* __restrict__ rowptr, int* __restrict__ off,
                  int* __restrict__ cnt, const int* __restrict__ bsum,
                  int nsb, int n)
{
    __shared__ int sb[32];
    int tid = threadIdx.x;
    if (tid < 32) {
        int v = (tid < nsb) ? bsum[tid] : 0;
        int s = v;
#pragma unroll
        for (int o = 1; o < 32; o <<= 1) {
            int t = __shfl_up_sync(0xffffffffu, s, o);
            if (tid >= o) s += t;
        }
        sb[tid] = s - v;
        if (blockIdx.x == 0 && tid == 31) rowptr[n] = s;
    }
    __syncthreads();
    int i = blockIdx.x * blockDim.x + tid;
    if (i >= n) return;
    int v = rowptr[i] + sb[i >> 12];
    rowptr[i] = v;
    off[i] = v;
    cnt[i] = 0;
}

__global__ void scatter_kernel(const int* __restrict__ src, const int* __restrict__ dst,
                               int* __restrict__ off, int* __restrict__ col, int ne)
{
    int i = blockIdx.x * blockDim.x + threadIdx.x;
    int j = 2 * i;
    if (j + 1 < ne) {
        int2 s = *(const int2*)&src[j];
        int2 d = *(const int2*)&dst[j];
        int p0 = atomicAdd(&off[d.x], 1);
        int p1 = atomicAdd(&off[d.y], 1);
        col[p0] = s.x;
        col[p1] = s.y;
    } else if (j < ne) {
        int pos = atomicAdd(&off[dst[j]], 1);
        col[pos] = src[j];
    }
}

// ---------------------------------------------------------------------------
// Node kernel: warp per destination in [base, nend), chunked lane-parallel
// weights, shfl broadcast, packed-f32x2 accumulation.
// ---------------------------------------------------------------------------
template <int F>
__global__ __launch_bounds__(256)
void node_kernel(const float* __restrict__ xl, const float* __restrict__ bias,
                 const int* __restrict__ rowptr, const int* __restrict__ col,
                 const float* __restrict__ asrc, const float* __restrict__ adst,
                 float* __restrict__ out, int base, int nend)
{
    constexpr int FT = 2 * F;
    const unsigned FULL = 0xffffffffu;
    int w = base + ((blockIdx.x * blockDim.x + threadIdx.x) >> 5);
    int lane = threadIdx.x & 31;
    if (w >= nend) return;

    const int beg = rowptr[w], end = rowptr[w + 1];
    const int deg = end - beg;
    const float ad0 = adst[2 * w], ad1 = adst[2 * w + 1];
    const float aself0 = leaky(asrc[2 * w] + ad0);
    const float aself1 = leaky(asrc[2 * w + 1] + ad1);

    ull A0 = 0ull, A1 = 0ull, A2 = 0ull, A3 = 0ull;
    const ulonglong2* xrow = (const ulonglong2*)(xl + (size_t)w * FT);
    float den0, den1;

    if (deg <= 32) {
        int i = beg + lane;
        bool vld = (i < end);
        int s_l = vld ? col[i] : 0;
        float al0 = -1e30f, al1 = -1e30f;
        if (vld) {
            al0 = leaky(asrc[2 * s_l]     + ad0);
            al1 = leaky(asrc[2 * s_l + 1] + ad1);
        }
        float m0 = fmaxf(al0, aself0), m1 = fmaxf(al1, aself1);
#pragma unroll
        for (int o = 16; o > 0; o >>= 1) {
            m0 = fmaxf(m0, __shfl_xor_sync(FULL, m0, o));
            m1 = fmaxf(m1, __shfl_xor_sync(FULL, m1, o));
        }
        float f0_l = vld ? __expf(al0 - m0) : 0.f;
        float f1_l = vld ? __expf(al1 - m1) : 0.f;
        float d0 = f0_l, d1 = f1_l;
#pragma unroll
        for (int o = 16; o > 0; o >>= 1) {
            d0 += __shfl_xor_sync(FULL, d0, o);
            d1 += __shfl_xor_sync(FULL, d1, o);
        }
        float e0 = __expf(aself0 - m0), e1 = __expf(aself1 - m1);
        den0 = d0 + e0; den1 = d1 + e1;

        if constexpr (F == 64) {
            ull ep = pack2((lane < 16) ? e0 : e1);
            ulonglong2 v = xrow[lane];
            fma_f32x2(A0, v.x, ep);
            fma_f32x2(A1, v.y, ep);
#pragma unroll 4
            for (int e = 0; e < deg; e++) {
                int s    = __shfl_sync(FULL, s_l, e);
                float f0 = __shfl_sync(FULL, f0_l, e);
                float f1 = __shfl_sync(FULL, f1_l, e);
                ull fp = pack2((lane < 16) ? f0 : f1);
                ulonglong2 u = ((const ulonglong2*)(xl + (size_t)s * FT))[lane];
                fma_f32x2(A0, u.x, fp);
                fma_f32x2(A1, u.y, fp);
            }
        } else {
            ull e0p = pack2(e0), e1p = pack2(e1);
            ulonglong2 v0 = xrow[lane], v1 = xrow[lane + 32];
            fma_f32x2(A0, v0.x, e0p); fma_f32x2(A1, v0.y, e0p);
            fma_f32x2(A2, v1.x, e1p); fma_f32x2(A3, v1.y, e1p);
#pragma unroll 4
            for (int e = 0; e < deg; e++) {
                int s    = __shfl_sync(FULL, s_l, e);
                float f0 = __shfl_sync(FULL, f0_l, e);
                float f1 = __shfl_sync(FULL, f1_l, e);
                ull f0p = pack2(f0), f1p = pack2(f1);
                const ulonglong2* xs = (const ulonglong2*)(xl + (size_t)s * FT);
                ulonglong2 u0 = xs[lane], u1 = xs[lane + 32];
                fma_f32x2(A0, u0.x, f0p); fma_f32x2(A1, u0.y, f0p);
                fma_f32x2(A2, u1.x, f1p); fma_f32x2(A3, u1.y, f1p);
            }
        }
    } else {
        float m0 = aself0, m1 = aself1;
        for (int i = beg + lane; i < end; i += 32) {
            int s = col[i];
            m0 = fmaxf(m0, leaky(asrc[2 * s]     + ad0));
            m1 = fmaxf(m1, leaky(asrc[2 * s + 1] + ad1));
        }
#pragma unroll
        for (int o = 16; o > 0; o >>= 1) {
            m0 = fmaxf(m0, __shfl_xor_sync(FULL, m0, o));
            m1 = fmaxf(m1, __shfl_xor_sync(FULL, m1, o));
        }
        float e0 = __expf(aself0 - m0), e1 = __expf(aself1 - m1);
        float dp0 = 0.f, dp1 = 0.f;

        if constexpr (F == 64) {
            ull ep = pack2((lane < 16) ? e0 : e1);
            ulonglong2 v = xrow[lane];
            fma_f32x2(A0, v.x, ep);
            fma_f32x2(A1, v.y, ep);
        } else {
            ull e0p = pack2(e0), e1p = pack2(e1);
            ulonglong2 v0 = xrow[lane], v1 = xrow[lane + 32];
            fma_f32x2(A0, v0.x, e0p); fma_f32x2(A1, v0.y, e0p);
            fma_f32x2(A2, v1.x, e1p); fma_f32x2(A3, v1.y, e1p);
        }

        for (int b2 = beg; b2 < end; b2 += 32) {
            int i = b2 + lane;
            bool vld = (i < end);
            int s_l = vld ? col[i] : 0;
            float f0_l = 0.f, f1_l = 0.f;
            if (vld) {
                f0_l = __expf(leaky(asrc[2 * s_l]     + ad0) - m0);
                f1_l = __expf(leaky(asrc[2 * s_l + 1] + ad1) - m1);
            }
            dp0 += f0_l; dp1 += f1_l;
            int cnt = min(32, end - b2);
#pragma unroll 4
            for (int e = 0; e < cnt; e++) {
                int s    = __shfl_sync(FULL, s_l, e);
                float f0 = __shfl_sync(FULL, f0_l, e);
                float f1 = __shfl_sync(FULL, f1_l, e);
                if constexpr (F == 64) {
                    ull fp = pack2((lane < 16) ? f0 : f1);
                    ulonglong2 u = ((const ulonglong2*)(xl + (size_t)s * FT))[lane];
                    fma_f32x2(A0, u.x, fp);
                    fma_f32x2(A1, u.y, fp);
                } else {
                    ull f0p = pack2(f0), f1p = pack2(f1);
                    const ulonglong2* xs = (const ulonglong2*)(xl + (size_t)s * FT);
                    ulonglong2 u0 = xs[lane], u1 = xs[lane + 32];
                    fma_f32x2(A0, u0.x, f0p); fma_f32x2(A1, u0.y, f0p);
                    fma_f32x2(A2, u1.x, f1p); fma_f32x2(A3, u1.y, f1p);
                }
            }
        }
#pragma unroll
        for (int o = 16; o > 0; o >>= 1) {
            dp0 += __shfl_xor_sync(FULL, dp0, o);
            dp1 += __shfl_xor_sync(FULL, dp1, o);
        }
        den0 = dp0 + e0; den1 = dp1 + e1;
    }

    const float4* b4 = (const float4*)bias;
    float4* orow = (float4*)(out + (size_t)w * FT);
    if constexpr (F == 64) {
        float id = 1.f / ((lane < 16) ? den0 : den1);
        float2 p0 = unpack2(A0), p1 = unpack2(A1);
        float4 bb = b4[lane];
        orow[lane] = make_float4(p0.x * id + bb.x, p0.y * id + bb.y,
                                 p1.x * id + bb.z, p1.y * id + bb.w);
    } else {
        float id0 = 1.f / den0, id1 = 1.f / den1;
        float2 p0 = unpack2(A0), p1 = unpack2(A1);
        float2 p2 = unpack2(A2), p3 = unpack2(A3);
        float4 b0 = b4[lane], b1 = b4[lane + 32];
        orow[lane]      = make_float4(p0.x * id0 + b0.x, p0.y * id0 + b0.y,
                                      p1.x * id0 + b0.z, p1.y * id0 + b0.w);
        orow[lane + 32] = make_float4(p2.x * id1 + b1.x, p2.y * id1 + b1.y,
                                      p3.x * id1 + b1.z, p3.y * id1 + b1.w);
    }
}

// ---------------------------------------------------------------------------

extern "C" void kernel_launch(void* const* d_in, const int* in_sizes, int n_in,
                              void* d_out, int out_size)
{
    const float* x   = (const float*)d_in[0];
    const int*   und = (const int*)d_in[1];
    const int*   dir = (const int*)d_in[2];
    const float* W1  = (const float*)d_in[3];
    const float* as1 = (const float*)d_in[4];
    const float* ad1 = (const float*)d_in[5];
    const float* b1  = (const float*)d_in[6];
    const float* W2  = (const float*)d_in[7];
    const float* as2 = (const float*)d_in[8];
    const float* ad2 = (const float*)d_in[9];
    const float* b2  = (const float*)d_in[10];
    float* out = (float*)d_out;

    const int n  = in_sizes[0] / 64;   // 50000
    const int e1 = in_sizes[1] / 2;    // 800000
    const int e2 = in_sizes[2] / 2;    // 800000

    float *xl1p, *out1p, *xl2p, *asrc1, *adst1, *asrc2, *adst2;
    int *cnt1, *cnt2, *rp1, *rp2, *off1, *off2, *col1, *col2, *bs1, *bs2;
    cudaGetSymbolAddress((void**)&xl1p,  g_xl1);
    cudaGetSymbolAddress((void**)&out1p, g_out1);
    cudaGetSymbolAddress((void**)&xl2p,  g_xl2);
    cudaGetSymbolAddress((void**)&asrc1, g_asrc1);
    cudaGetSymbolAddress((void**)&adst1, g_adst1);
    cudaGetSymbolAddress((void**)&asrc2, g_asrc2);
    cudaGetSymbolAddress((void**)&adst2, g_adst2);
    cudaGetSymbolAddress((void**)&cnt1, g_cnt1);
    cudaGetSymbolAddress((void**)&cnt2, g_cnt2);
    cudaGetSymbolAddress((void**)&rp1,  g_rowptr1);
    cudaGetSymbolAddress((void**)&rp2,  g_rowptr2);
    cudaGetSymbolAddress((void**)&off1, g_off1);
    cudaGetSymbolAddress((void**)&off2, g_off2);
    cudaGetSymbolAddress((void**)&col1, g_col1);
    cudaGetSymbolAddress((void**)&col2, g_col2);
    cudaGetSymbolAddress((void**)&bs1,  g_bsum1);
    cudaGetSymbolAddress((void**)&bs2,  g_bsum2);

    const int T = 256;
    auto cdiv = [](long long a, long long b) { return (int)((a + b - 1) / b); };
    const int nsb = cdiv(n, 4096);
    const int h = ((int)(0.45 * n) / 64) * 64;     // gemm2 / node1 split point

    static cudaStream_t sA = nullptr, sB = nullptr, sC = nullptr;
    static cudaEvent_t evRoot = nullptr, evB1 = nullptr, evB2 = nullptr,
                       evN1a = nullptr, evG2a = nullptr;
    if (!sA) {
        cudaStreamCreateWithFlags(&sA, cudaStreamNonBlocking);
        cudaStreamCreateWithFlags(&sB, cudaStreamNonBlocking);
        cudaStreamCreateWithFlags(&sC, cudaStreamNonBlocking);
        cudaEventCreateWithFlags(&evRoot, cudaEventDisableTiming);
        cudaEventCreateWithFlags(&evB1, cudaEventDisableTiming);
        cudaEventCreateWithFlags(&evB2, cudaEventDisableTiming);
        cudaEventCreateWithFlags(&evN1a, cudaEventDisableTiming);
        cudaEventCreateWithFlags(&evG2a, cudaEventDisableTiming);
    }

    cudaEventRecord(evRoot, 0);
    cudaStreamWaitEvent(sB, evRoot, 0);
    cudaStreamWaitEvent(sC, evRoot, 0);

    // stream B: layer-1 CSR
    hist_kernel<<<cdiv(cdiv(e1, 2), T), T, 0, sB>>>(und + e1, cnt1, e1);
    scanA_kernel<<<nsb, 1024, 0, sB>>>(cnt1, rp1, bs1, n);
    scanC_kernel<<<cdiv(n, T), T, 0, sB>>>(rp1, off1, cnt1, bs1, nsb, n);
    scatter_kernel<<<cdiv(cdiv(e1, 2), T), T, 0, sB>>>(und, und + e1, off1, col1, e1);
    cudaEventRecord(evB1, sB);

    // stream C: layer-2 CSR
    hist_kernel<<<cdiv(cdiv(e2, 2), T), T, 0, sC>>>(dir + e2, cnt2, e2);
    scanA_kernel<<<nsb, 1024, 0, sC>>>(cnt2, rp2, bs2, n);
    scanC_kernel<<<cdiv(n, T), T, 0, sC>>>(rp2, off2, cnt2, bs2, nsb, n);
    scatter_kernel<<<cdiv(cdiv(e2, 2), T), T, 0, sC>>>(dir, dir + e2, off2, col2, e2);
    cudaEventRecord(evB2, sC);

    // main chain
    gemm_kernel<64, 128><<<cdiv(n, 64), T>>>(x, W1, as1, ad1, asrc1, adst1, xl1p, 0, n);
    cudaStreamWaitEvent(0, evB1, 0);
    node_kernel<64><<<cdiv((long long)h * 32, T), T>>>(xl1p, b1, rp1, col1,
                                                       asrc1, adst1, out1p, 0, h);
    cudaEventRecord(evN1a, 0);
    node_kernel<64><<<cdiv((long long)(n - h) * 32, T), T>>>(xl1p, b1, rp1, col1,
                                                             asrc1, adst1, out1p, h, n);

    // side stream: gemm2 on rows [0, h) overlapping node1b
    cudaStreamWaitEvent(sA, evN1a, 0);
    gemm_kernel<128, 256><<<cdiv(h, 64), T, 0, sA>>>(out1p, W2, as2, ad2,
                                                     asrc2, adst2, xl2p, 0, h);
    cudaEventRecord(evG2a, sA);

    // main: gemm2 on rows [h, n)
    gemm_kernel<128, 256><<<cdiv(n - h, 64), T>>>(out1p, W2, as2, ad2,
                                                  asrc2, adst2, xl2p, h, n);
    cudaStreamWaitEvent(0, evG2a, 0);
    cudaStreamWaitEvent(0, evB2, 0);
    node_kernel<128><<<cdiv((long long)n * 32, T), T>>>(xl2p, b2, rp2, col2,
                                                        asrc2, adst2, out, 0, n);
}

// round 17
// speedup vs baseline: 1.0452x; 1.0452x over previous
#include <cuda_runtime.h>
#include <cstdint>

// ---------------------------------------------------------------------------
// 2-layer GAT (heads=2), CSR-based. FFMA2 GEMM with fused attention epilogue,
// packed-f32x2 node softmax-aggregate. CSR builds on high-priority side
// streams overlapping the GEMM/node chain in the captured graph.
// ---------------------------------------------------------------------------

#define NN 50000
#define NE 800000

typedef unsigned long long ull;

__device__ float g_xl1[NN * 128];
__device__ float g_out1[NN * 128];
__device__ float g_xl2[NN * 256];
__device__ float g_asrc1[NN * 2];
__device__ float g_adst1[NN * 2];
__device__ float g_asrc2[NN * 2];
__device__ float g_adst2[NN * 2];

// per-layer CSR buffers (cnt must be zero at entry; scanC re-zeroes)
__device__ int g_cnt1[NN],  g_cnt2[NN];
__device__ int g_rowptr1[NN + 1], g_rowptr2[NN + 1];
__device__ int g_off1[NN],  g_off2[NN];
__device__ int g_col1[NE],  g_col2[NE];
__device__ int g_bsum1[32], g_bsum2[32];

__device__ __forceinline__ float leaky(float a) { return a > 0.f ? a : 0.2f * a; }

__device__ __forceinline__ void fma_f32x2(ull& c, ull a, ull b) {
    asm("fma.rn.f32x2 %0, %1, %2, %0;" : "+l"(c) : "l"(a), "l"(b));
}
__device__ __forceinline__ float2 unpack2(ull v) {
    float lo, hi;
    asm("mov.b64 {%0,%1}, %2;" : "=f"(lo), "=f"(hi) : "l"(v));
    return make_float2(lo, hi);
}
__device__ __forceinline__ ull pack2(float f) {
    ull r;
    asm("mov.b64 %0, {%1,%1};" : "=l"(r) : "f"(f));
    return r;
}

// ---------------------------------------------------------------------------
// Packed GEMM + fused attention epilogue.
// ---------------------------------------------------------------------------
template <int KTOT, int NC>
__global__ __launch_bounds__(256)
void gemm_kernel(const float* __restrict__ A, const float* __restrict__ B,
                 const float* __restrict__ att_s, const float* __restrict__ att_d,
                 float* __restrict__ asrc, float* __restrict__ adst,
                 float* __restrict__ C, int M)
{
    constexpr int TM = 64, BK = 32;
    constexpr int RM = 8;
    constexpr int RN2 = NC / 64;
    const unsigned FULL = 0xffffffffu;

    __shared__ float2 sA2[BK][TM + 1];
    __shared__ float  sB[BK][NC];

    const int tid = threadIdx.x;
    const int tx = tid & 31, ty = tid >> 5;
    const int m0 = blockIdx.x * TM;

    ull acc2[RM][RN2];
#pragma unroll
    for (int i = 0; i < RM; i++)
#pragma unroll
        for (int j = 0; j < RN2; j++) acc2[i][j] = 0ull;

    for (int k0 = 0; k0 < KTOT; k0 += BK) {
#pragma unroll
        for (int i = 0; i < (TM * BK) / 256; i++) {
            int idx = tid + 256 * i;
            int r = idx >> 5;
            int kk = idx & 31;
            int row = m0 + r;
            float v = (row < M) ? A[(size_t)row * KTOT + k0 + kk] : 0.f;
            sA2[kk][r] = make_float2(v, v);
        }
#pragma unroll
        for (int i = 0; i < (BK * NC) / 256; i++) {
            int idx = tid + 256 * i;
            int kk = idx / NC;
            int c  = idx % NC;
            sB[kk][c] = B[(size_t)(k0 + kk) * NC + c];
        }
        __syncthreads();

#pragma unroll 4
        for (int kk = 0; kk < BK; kk++) {
            ull xv[RM], wv[RN2];
#pragma unroll
            for (int i = 0; i < RM; i++)
                xv[i] = *(const ull*)&sA2[kk][ty * RM + i];
#pragma unroll
            for (int j = 0; j < RN2; j++)
                wv[j] = *(const ull*)&sB[kk][64 * j + 2 * tx];
#pragma unroll
            for (int i = 0; i < RM; i++)
#pragma unroll
                for (int j = 0; j < RN2; j++)
                    fma_f32x2(acc2[i][j], xv[i], wv[j]);
        }
        __syncthreads();
    }

    float2 asv[RN2], adv[RN2];
#pragma unroll
    for (int j = 0; j < RN2; j++) {
        asv[j] = *(const float2*)&att_s[64 * j + 2 * tx];
        adv[j] = *(const float2*)&att_d[64 * j + 2 * tx];
    }
#pragma unroll
    for (int i = 0; i < RM; i++) {
        int row = m0 + ty * RM + i;
        if (row >= M) continue;
        float s0 = 0.f, s1 = 0.f, d0 = 0.f, d1 = 0.f;
#pragma unroll
        for (int j = 0; j < RN2; j++) {
            float2 c = unpack2(acc2[i][j]);
            *(float2*)&C[(size_t)row * NC + 64 * j + 2 * tx] = c;
            float ps = c.x * asv[j].x + c.y * asv[j].y;
            float pd = c.x * adv[j].x + c.y * adv[j].y;
            if (j < RN2 / 2) { s0 += ps; d0 += pd; }
            else             { s1 += ps; d1 += pd; }
        }
#pragma unroll
        for (int o = 16; o > 0; o >>= 1) {
            s0 += __shfl_xor_sync(FULL, s0, o);
            s1 += __shfl_xor_sync(FULL, s1, o);
            d0 += __shfl_xor_sync(FULL, d0, o);
            d1 += __shfl_xor_sync(FULL, d1, o);
        }
        if (tx == 0) {
            asrc[2 * row] = s0; asrc[2 * row + 1] = s1;
            adst[2 * row] = d0; adst[2 * row + 1] = d1;
        }
    }
}

// ---------------------------------------------------------------------------
// CSR construction (scalar hist/scatter — measured best form).
// ---------------------------------------------------------------------------
__global__ void hist_kernel(const int* __restrict__ dst, int* __restrict__ cnt, int ne)
{
    int i = blockIdx.x * blockDim.x + threadIdx.x;
    if (i < ne) atomicAdd(&cnt[dst[i]], 1);
}

__global__ __launch_bounds__(1024)
void scanA_kernel(const int* __restrict__ cnt, int* __restrict__ rowptr,
                  int* __restrict__ bsum, int n)
{
    __shared__ int wsum[32];
    int tid = threadIdx.x, lane = tid & 31, wid = tid >> 5;
    int i0 = blockIdx.x * 4096 + tid * 4;

    int c0 = 0, c1 = 0, c2 = 0, c3 = 0;
    if (i0 + 3 < n) {
        int4 t = *(const int4*)&cnt[i0];
        c0 = t.x; c1 = t.y; c2 = t.z; c3 = t.w;
    } else {
        if (i0     < n) c0 = cnt[i0];
        if (i0 + 1 < n) c1 = cnt[i0 + 1];
        if (i0 + 2 < n) c2 = cnt[i0 + 2];
        if (i0 + 3 < n) c3 = cnt[i0 + 3];
    }
    int v = c0 + c1 + c2 + c3;
    int s = v;
#pragma unroll
    for (int o = 1; o < 32; o <<= 1) {
        int t = __shfl_up_sync(0xffffffffu, s, o);
        if (lane >= o) s += t;
    }
    if (lane == 31) wsum[wid] = s;
    __syncthreads();
    if (wid == 0) {
        int ws = wsum[lane];
#pragma unroll
        for (int o = 1; o < 32; o <<= 1) {
            int t = __shfl_up_sync(0xffffffffu, ws, o);
            if (lane >= o) ws += t;
        }
        wsum[lane] = ws;
    }
    __syncthreads();
    int excl = s - v + (wid ? wsum[wid - 1] : 0);
    int e0 = excl, e1 = e0 + c0, e2 = e1 + c1, e3 = e2 + c2;
    if (i0     < n) rowptr[i0]     = e0;
    if (i0 + 1 < n) rowptr[i0 + 1] = e1;
    if (i0 + 2 < n) rowptr[i0 + 2] = e2;
    if (i0 + 3 < n) rowptr[i0 + 3] = e3;
    if (tid == 0) bsum[blockIdx.x] = wsum[31];
}

// scanC with fused scanB: warp 0 of every block redundantly scans bsum.
__global__ __launch_bounds__(256)
void scanC_kernel(int* __restrict__ rowptr, int* __restrict__ off,
                  int* __restrict__ cnt, const int* __restrict__ bsum,
                  int nsb, int n)
{
    __shared__ int sb[32];
    int tid = threadIdx.x;
    if (tid < 32) {
        int v = (tid < nsb) ? bsum[tid] : 0;
        int s = v;
#pragma unroll
        for (int o = 1; o < 32; o <<= 1) {
            int t = __shfl_up_sync(0xffffffffu, s, o);
            if (tid >= o) s += t;
        }
        sb[tid] = s - v;
        if (blockIdx.x == 0 && tid == 31) rowptr[n] = s;
    }
    __syncthreads();
    int i = blockIdx.x * blockDim.x + tid;
    if (i >= n) return;
    int v = rowptr[i] + sb[i >> 12];
    rowptr[i] = v;
    off[i] = v;
    cnt[i] = 0;
}

__global__ void scatter_kernel(const int* __restrict__ src, const int* __restrict__ dst,
                               int* __restrict__ off, int* __restrict__ col, int ne)
{
    int i = blockIdx.x * blockDim.x + threadIdx.x;
    if (i >= ne) return;
    int pos = atomicAdd(&off[dst[i]], 1);
    col[pos] = src[i];
}

// ---------------------------------------------------------------------------
// Node kernel: warp per destination, chunked lane-parallel weights, shfl
// broadcast, packed-f32x2 accumulation, deep unroll for gather MLP.
// ---------------------------------------------------------------------------
template <int F>
__global__ __launch_bounds__(256)
void node_kernel(const float* __restrict__ xl, const float* __restrict__ bias,
                 const int* __restrict__ rowptr, const int* __restrict__ col,
                 const float* __restrict__ asrc, const float* __restrict__ adst,
                 float* __restrict__ out, int n_nodes)
{
    constexpr int FT = 2 * F;
    const unsigned FULL = 0xffffffffu;
    int w = (blockIdx.x * blockDim.x + threadIdx.x) >> 5;
    int lane = threadIdx.x & 31;
    if (w >= n_nodes) return;

    const int beg = rowptr[w], end = rowptr[w + 1];
    const int deg = end - beg;
    const float ad0 = adst[2 * w], ad1 = adst[2 * w + 1];
    const float aself0 = leaky(asrc[2 * w] + ad0);
    const float aself1 = leaky(asrc[2 * w + 1] + ad1);

    ull A0 = 0ull, A1 = 0ull, A2 = 0ull, A3 = 0ull;
    const ulonglong2* xrow = (const ulonglong2*)(xl + (size_t)w * FT);
    float den0, den1;

    if (deg <= 32) {
        int i = beg + lane;
        bool vld = (i < end);
        int s_l = vld ? col[i] : 0;
        float al0 = -1e30f, al1 = -1e30f;
        if (vld) {
            al0 = leaky(asrc[2 * s_l]     + ad0);
            al1 = leaky(asrc[2 * s_l + 1] + ad1);
        }
        float m0 = fmaxf(al0, aself0), m1 = fmaxf(al1, aself1);
#pragma unroll
        for (int o = 16; o > 0; o >>= 1) {
            m0 = fmaxf(m0, __shfl_xor_sync(FULL, m0, o));
            m1 = fmaxf(m1, __shfl_xor_sync(FULL, m1, o));
        }
        float f0_l = vld ? __expf(al0 - m0) : 0.f;
        float f1_l = vld ? __expf(al1 - m1) : 0.f;
        float d0 = f0_l, d1 = f1_l;
#pragma unroll
        for (int o = 16; o > 0; o >>= 1) {
            d0 += __shfl_xor_sync(FULL, d0, o);
            d1 += __shfl_xor_sync(FULL, d1, o);
        }
        float e0 = __expf(aself0 - m0), e1 = __expf(aself1 - m1);
        den0 = d0 + e0; den1 = d1 + e1;

        if constexpr (F == 64) {
            ull ep = pack2((lane < 16) ? e0 : e1);
            ulonglong2 v = xrow[lane];
            fma_f32x2(A0, v.x, ep);
            fma_f32x2(A1, v.y, ep);
#pragma unroll 8
            for (int e = 0; e < deg; e++) {
                int s    = __shfl_sync(FULL, s_l, e);
                float f0 = __shfl_sync(FULL, f0_l, e);
                float f1 = __shfl_sync(FULL, f1_l, e);
                ull fp = pack2((lane < 16) ? f0 : f1);
                ulonglong2 u = ((const ulonglong2*)(xl + (size_t)s * FT))[lane];
                fma_f32x2(A0, u.x, fp);
                fma_f32x2(A1, u.y, fp);
            }
        } else {
            ull e0p = pack2(e0), e1p = pack2(e1);
            ulonglong2 v0 = xrow[lane], v1 = xrow[lane + 32];
            fma_f32x2(A0, v0.x, e0p); fma_f32x2(A1, v0.y, e0p);
            fma_f32x2(A2, v1.x, e1p); fma_f32x2(A3, v1.y, e1p);
#pragma unroll 8
            for (int e = 0; e < deg; e++) {
                int s    = __shfl_sync(FULL, s_l, e);
                float f0 = __shfl_sync(FULL, f0_l, e);
                float f1 = __shfl_sync(FULL, f1_l, e);
                ull f0p = pack2(f0), f1p = pack2(f1);
                const ulonglong2* xs = (const ulonglong2*)(xl + (size_t)s * FT);
                ulonglong2 u0 = xs[lane], u1 = xs[lane + 32];
                fma_f32x2(A0, u0.x, f0p); fma_f32x2(A1, u0.y, f0p);
                fma_f32x2(A2, u1.x, f1p); fma_f32x2(A3, u1.y, f1p);
            }
        }
    } else {
        float m0 = aself0, m1 = aself1;
        for (int i = beg + lane; i < end; i += 32) {
            int s = col[i];
            m0 = fmaxf(m0, leaky(asrc[2 * s]     + ad0));
            m1 = fmaxf(m1, leaky(asrc[2 * s + 1] + ad1));
        }
#pragma unroll
        for (int o = 16; o > 0; o >>= 1) {
            m0 = fmaxf(m0, __shfl_xor_sync(FULL, m0, o));
            m1 = fmaxf(m1, __shfl_xor_sync(FULL, m1, o));
        }
        float e0 = __expf(aself0 - m0), e1 = __expf(aself1 - m1);
        float dp0 = 0.f, dp1 = 0.f;

        if constexpr (F == 64) {
            ull ep = pack2((lane < 16) ? e0 : e1);
            ulonglong2 v = xrow[lane];
            fma_f32x2(A0, v.x, ep);
            fma_f32x2(A1, v.y, ep);
        } else {
            ull e0p = pack2(e0), e1p = pack2(e1);
            ulonglong2 v0 = xrow[lane], v1 = xrow[lane + 32];
            fma_f32x2(A0, v0.x, e0p); fma_f32x2(A1, v0.y, e0p);
            fma_f32x2(A2, v1.x, e1p); fma_f32x2(A3, v1.y, e1p);
        }

        for (int b2 = beg; b2 < end; b2 += 32) {
            int i = b2 + lane;
            bool vld = (i < end);
            int s_l = vld ? col[i] : 0;
            float f0_l = 0.f, f1_l = 0.f;
            if (vld) {
                f0_l = __expf(leaky(asrc[2 * s_l]     + ad0) - m0);
                f1_l = __expf(leaky(asrc[2 * s_l + 1] + ad1) - m1);
            }
            dp0 += f0_l; dp1 += f1_l;
            int cnt = min(32, end - b2);
#pragma unroll 4
            for (int e = 0; e < cnt; e++) {
                int s    = __shfl_sync(FULL, s_l, e);
                float f0 = __shfl_sync(FULL, f0_l, e);
                float f1 = __shfl_sync(FULL, f1_l, e);
                if constexpr (F == 64) {
                    ull fp = pack2((lane < 16) ? f0 : f1);
                    ulonglong2 u = ((const ulonglong2*)(xl + (size_t)s * FT))[lane];
                    fma_f32x2(A0, u.x, fp);
                    fma_f32x2(A1, u.y, fp);
                } else {
                    ull f0p = pack2(f0), f1p = pack2(f1);
                    const ulonglong2* xs = (const ulonglong2*)(xl + (size_t)s * FT);
                    ulonglong2 u0 = xs[lane], u1 = xs[lane + 32];
                    fma_f32x2(A0, u0.x, f0p); fma_f32x2(A1, u0.y, f0p);
                    fma_f32x2(A2, u1.x, f1p); fma_f32x2(A3, u1.y, f1p);
                }
            }
        }
#pragma unroll
        for (int o = 16; o > 0; o >>= 1) {
            dp0 += __shfl_xor_sync(FULL, dp0, o);
            dp1 += __shfl_xor_sync(FULL, dp1, o);
        }
        den0 = dp0 + e0; den1 = dp1 + e1;
    }

    const float4* b4 = (const float4*)bias;
    float4* orow = (float4*)(out + (size_t)w * FT);
    if constexpr (F == 64) {
        float id = 1.f / ((lane < 16) ? den0 : den1);
        float2 p0 = unpack2(A0), p1 = unpack2(A1);
        float4 bb = b4[lane];
        orow[lane] = make_float4(p0.x * id + bb.x, p0.y * id + bb.y,
                                 p1.x * id + bb.z, p1.y * id + bb.w);
    } else {
        float id0 = 1.f / den0, id1 = 1.f / den1;
        float2 p0 = unpack2(A0), p1 = unpack2(A1);
        float2 p2 = unpack2(A2), p3 = unpack2(A3);
        float4 b0 = b4[lane], b1 = b4[lane + 32];
        orow[lane]      = make_float4(p0.x * id0 + b0.x, p0.y * id0 + b0.y,
                                      p1.x * id0 + b0.z, p1.y * id0 + b0.w);
        orow[lane + 32] = make_float4(p2.x * id1 + b1.x, p2.y * id1 + b1.y,
                                      p3.x * id1 + b1.z, p3.y * id1 + b1.w);
    }
}

// ---------------------------------------------------------------------------

extern "C" void kernel_launch(void* const* d_in, const int* in_sizes, int n_in,
                              void* d_out, int out_size)
{
    const float* x   = (const float*)d_in[0];
    const int*   und = (const int*)d_in[1];
    const int*   dir = (const int*)d_in[2];
    const float* W1  = (const float*)d_in[3];
    const float* as1 = (const float*)d_in[4];
    const float* ad1 = (const float*)d_in[5];
    const float* b1  = (const float*)d_in[6];
    const float* W2  = (const float*)d_in[7];
    const float* as2 = (const float*)d_in[8];
    const float* ad2 = (const float*)d_in[9];
    const float* b2  = (const float*)d_in[10];
    float* out = (float*)d_out;

    const int n  = in_sizes[0] / 64;   // 50000
    const int e1 = in_sizes[1] / 2;    // 800000
    const int e2 = in_sizes[2] / 2;    // 800000

    float *xl1p, *out1p, *xl2p, *asrc1, *adst1, *asrc2, *adst2;
    int *cnt1, *cnt2, *rp1, *rp2, *off1, *off2, *col1, *col2, *bs1, *bs2;
    cudaGetSymbolAddress((void**)&xl1p,  g_xl1);
    cudaGetSymbolAddress((void**)&out1p, g_out1);
    cudaGetSymbolAddress((void**)&xl2p,  g_xl2);
    cudaGetSymbolAddress((void**)&asrc1, g_asrc1);
    cudaGetSymbolAddress((void**)&adst1, g_adst1);
    cudaGetSymbolAddress((void**)&asrc2, g_asrc2);
    cudaGetSymbolAddress((void**)&adst2, g_adst2);
    cudaGetSymbolAddress((void**)&cnt1, g_cnt1);
    cudaGetSymbolAddress((void**)&cnt2, g_cnt2);
    cudaGetSymbolAddress((void**)&rp1,  g_rowptr1);
    cudaGetSymbolAddress((void**)&rp2,  g_rowptr2);
    cudaGetSymbolAddress((void**)&off1, g_off1);
    cudaGetSymbolAddress((void**)&off2, g_off2);
    cudaGetSymbolAddress((void**)&col1, g_col1);
    cudaGetSymbolAddress((void**)&col2, g_col2);
    cudaGetSymbolAddress((void**)&bs1,  g_bsum1);
    cudaGetSymbolAddress((void**)&bs2,  g_bsum2);

    const int T = 256;
    auto cdiv = [](long long a, long long b) { return (int)((a + b - 1) / b); };
    const int nsb = cdiv(n, 4096);

    // persistent streams (CSR streams at highest priority) + events
    static cudaStream_t sB = nullptr, sC = nullptr;
    static cudaEvent_t evRoot = nullptr, evB1 = nullptr, evB2 = nullptr;
    if (!sB) {
        int leastP = 0, greatestP = 0;
        cudaDeviceGetStreamPriorityRange(&leastP, &greatestP);
        cudaStreamCreateWithPriority(&sB, cudaStreamNonBlocking, greatestP);
        cudaStreamCreateWithPriority(&sC, cudaStreamNonBlocking, greatestP);
        cudaEventCreateWithFlags(&evRoot, cudaEventDisableTiming);
        cudaEventCreateWithFlags(&evB1, cudaEventDisableTiming);
        cudaEventCreateWithFlags(&evB2, cudaEventDisableTiming);
    }

    cudaEventRecord(evRoot, 0);
    cudaStreamWaitEvent(sB, evRoot, 0);
    cudaStreamWaitEvent(sC, evRoot, 0);

    // stream B (high prio): layer-1 CSR — this is the critical-path head
    hist_kernel<<<cdiv(e1, T), T, 0, sB>>>(und + e1, cnt1, e1);
    scanA_kernel<<<nsb, 1024, 0, sB>>>(cnt1, rp1, bs1, n);
    scanC_kernel<<<cdiv(n, T), T, 0, sB>>>(rp1, off1, cnt1, bs1, nsb, n);
    scatter_kernel<<<cdiv(e1, T), T, 0, sB>>>(und, und + e1, off1, col1, e1);
    cudaEventRecord(evB1, sB);

    // stream C (high prio): layer-2 CSR
    hist_kernel<<<cdiv(e2, T), T, 0, sC>>>(dir + e2, cnt2, e2);
    scanA_kernel<<<nsb, 1024, 0, sC>>>(cnt2, rp2, bs2, n);
    scanC_kernel<<<cdiv(n, T), T, 0, sC>>>(rp2, off2, cnt2, bs2, nsb, n);
    scatter_kernel<<<cdiv(e2, T), T, 0, sC>>>(dir, dir + e2, off2, col2, e2);
    cudaEventRecord(evB2, sC);

    // main chain
    gemm_kernel<64, 128><<<cdiv(n, 64), T>>>(x, W1, as1, ad1, asrc1, adst1, xl1p, n);
    cudaStreamWaitEvent(0, evB1, 0);
    node_kernel<64><<<cdiv((long long)n * 32, T), T>>>(xl1p, b1, rp1, col1,
                                                       asrc1, adst1, out1p, n);

    gemm_kernel<128, 256><<<cdiv(n, 64), T>>>(out1p, W2, as2, ad2, asrc2, adst2, xl2p, n);
    cudaStreamWaitEvent(0, evB2, 0);
    node_kernel<128><<<cdiv((long long)n * 32, T), T>>>(xl2p, b2, rp2, col2,
                                                        asrc2, adst2, out, n);
}